// round 16
// baseline (speedup 1.0000x reference)
#include <cuda_runtime.h>
#include <cuda_fp16.h>
#include <math.h>
#include <stdint.h>
#include <mma.h>

using namespace nvcuda;

// ---------------- problem constants ----------------
#define D_DIM   1024
#define F_DIM   704
#define E_NUM   64
#define NTOK    1024
#define TOPK    6
#define FS_DIM  1408
#define NPAIR   (NTOK*TOPK)

// ---------------- scratch (static device arrays) ----------------
__device__ __half g_xh[NTOK * D_DIM];        // fp16 copy of x
__device__ __half g_hbuf[NPAIR * F_DIM];     // fp16 up-proj activations
__device__ float  g_dbuf[NPAIR * D_DIM];
__device__ __half g_sh[NTOK * FS_DIM];       // fp16 shared-expert hidden
__device__ int    g_count[E_NUM];
__device__ int    g_offset[E_NUM];
__device__ int    g_cursor[E_NUM];
__device__ int    g_tok_expert[NTOK*TOPK];
__device__ float  g_tok_w[NTOK*TOPK];
__device__ int    g_tok_pair[NTOK*TOPK];
__device__ int    g_pair_token[NPAIR];
__device__ float  g_pair_w[NPAIR];
__device__ float  g_scores_scratch[NTOK * E_NUM];

// ---------------- smem geometry ----------------
#define LDA_H 40     // halfs per A row (32 + 8 pad); 80 B = 16B-aligned rows
#define LDB_H 72     // halfs per B row (64 + 8 pad)
#define LDC   68     // floats per C row
#define NST   3      // 3-stage ring (cp.async writes 2 ahead of MMA reads)
// up stage (halfs): A 128*40=5120 @0, B1 32*72=2304 @5120, B2 @7424 -> 9728
#define STG_UP_H 9728
#define TOK_OFF_B (NST*STG_UP_H*2)           // 58368
#define SMEM_UP_B (TOK_OFF_B + 512)          // 58880
// down stage (halfs): A 5120 + B 2304 = 7424
#define STG_DN_H 7424
#define SMEM_DN_B (NST*STG_DN_H*2)           // 44544

// ---------------- cp.async helpers ----------------
__device__ __forceinline__ void cp16(uint32_t s, const void* g) {
    asm volatile("cp.async.cg.shared.global [%0], [%1], 16;" :: "r"(s), "l"(g));
}
__device__ __forceinline__ void cp_commit() {
    asm volatile("cp.async.commit_group;" ::: "memory");
}
template<int N> __device__ __forceinline__ void cp_wait() {
    asm volatile("cp.async.wait_group %0;" :: "n"(N) : "memory");
}

// ---------------- WMMA fp16 ----------------
using FragA = wmma::fragment<wmma::matrix_a, 16, 16, 16, __half, wmma::row_major>;
using FragB = wmma::fragment<wmma::matrix_b, 16, 16, 16, __half, wmma::row_major>;
using FragC = wmma::fragment<wmma::accumulator, 16, 16, 16, float>;

__device__ __forceinline__ void sts_f4_h4(__half* dst, float4 v) {
    __half2 p0 = __floats2half2_rn(v.x, v.y);
    __half2 p1 = __floats2half2_rn(v.z, v.w);
    uint2 u = make_uint2(*(uint32_t*)&p0, *(uint32_t*)&p1);
    *(uint2*)dst = u;
}

// ---------------- small kernels ----------------
__global__ void init_kernel() {
    int i = threadIdx.x;
    if (i < E_NUM) { g_count[i] = 0; g_cursor[i] = 0; }
}

// gate + top-k; also emits fp16 copy of x
__global__ void gate_kernel(const float* __restrict__ x,
                            const float* __restrict__ wg,
                            const float* __restrict__ gb,
                            float* __restrict__ scores_out) {
    __shared__ float xs[D_DIM];
    __shared__ float sc[E_NUM];
    int t = blockIdx.x;
    int tid = threadIdx.x;

    const float4* xv = (const float4*)(x + (size_t)t * D_DIM);
    float4* xsv = (float4*)xs;
    for (int i = tid; i < D_DIM/4; i += 128) xsv[i] = xv[i];
    __syncthreads();

    // fp16 copy (RN, identical rounding to the old STS-convert path)
    __half2* xh2 = (__half2*)(g_xh + (size_t)t * D_DIM);
    for (int i = tid; i < D_DIM/2; i += 128)
        xh2[i] = __floats2half2_rn(xs[2*i], xs[2*i+1]);

    if (tid < E_NUM) {
        const float4* wv = (const float4*)(wg + (size_t)tid * D_DIM);
        float acc = 0.f;
        #pragma unroll 8
        for (int i = 0; i < D_DIM/4; i++) {
            float4 a = xsv[i]; float4 b = wv[i];
            acc += a.x*b.x + a.y*b.y + a.z*b.z + a.w*b.w;
        }
        float s = 1.f/(1.f + expf(-acc)) + gb[tid];
        sc[tid] = s;
        scores_out[(size_t)t * E_NUM + tid] = s;
    }
    __syncthreads();

    if (tid == 0) {
        float tmp[E_NUM];
        for (int i = 0; i < E_NUM; i++) tmp[i] = sc[i];
        int   sel[TOPK]; float selw[TOPK];
        float wsum = 0.f;
        for (int k = 0; k < TOPK; k++) {
            int bi = 0; float bv = tmp[0];
            for (int i = 1; i < E_NUM; i++)
                if (tmp[i] > bv) { bv = tmp[i]; bi = i; }
            sel[k] = bi; selw[k] = bv; wsum += bv;
            tmp[bi] = -1e30f;
        }
        float inv = 1.f / wsum;
        for (int k = 0; k < TOPK; k++) {
            int e = sel[k];
            g_tok_expert[t*TOPK + k] = e;
            g_tok_w[t*TOPK + k] = selw[k] * inv;
            atomicAdd(&g_count[e], 1);
        }
    }
}

__global__ void scan_assign_kernel() {
    if (threadIdx.x == 0) {
        int acc = 0;
        for (int e = 0; e < E_NUM; e++) { g_offset[e] = acc; acc += g_count[e]; }
    }
    __syncthreads();
    int t = threadIdx.x;
    #pragma unroll
    for (int k = 0; k < TOPK; k++) {
        int e = g_tok_expert[t*TOPK + k];
        int slot = atomicAdd(&g_cursor[e], 1);
        int p = g_offset[e] + slot;
        g_pair_token[p] = t;
        g_pair_w[p] = g_tok_w[t*TOPK + k];
        g_tok_pair[t*TOPK + k] = p;
    }
}

// ===========================================================================
// Fused up-proj (fp16 MMA): routed (y<64) + shared (y==64).
// A via cp.async fp16 (g_xh), B via reg-stage+cvt. 3-stage ring.
// 256 thr, 8 warps 4x2, BM=128 BN=64 BK=32, 2 CTAs/SM. grid (22, 65, 8).
// ===========================================================================
__global__ void __launch_bounds__(256, 2)
up_fused(const float* __restrict__ w1r,
         const float* __restrict__ w3r,
         const float* __restrict__ w1s,
         const float* __restrict__ w3s) {
    extern __shared__ __half smh[];
    const int tid = threadIdx.x;
    const int y = blockIdx.y;
    const bool se = (y == E_NUM);
    const int f0 = blockIdx.x * 64;
    const int row0 = blockIdx.z * 128;

    int cnt, base, ldB, ldD;
    const float *B1, *B2;
    __half* dstbuf;
    if (se) {
        cnt = NTOK; base = 0;
        B1 = w1s; B2 = w3s; ldB = FS_DIM;
        dstbuf = g_sh; ldD = FS_DIM;
    } else {
        if (f0 >= F_DIM) return;
        cnt = g_count[y];
        if (row0 >= cnt) return;
        base = g_offset[y];
        B1 = w1r + (size_t)y * D_DIM * F_DIM;
        B2 = w3r + (size_t)y * D_DIM * F_DIM;
        ldB = F_DIM;
        dstbuf = g_hbuf; ldD = F_DIM;
    }

    int* toks = (int*)((char*)smh + TOK_OFF_B);
    if (tid < 128) {
        int r = row0 + tid;
        if (se) toks[tid] = r;
        else    toks[tid] = (r < cnt) ? g_pair_token[base + r] : 0;
    }
    __syncthreads();

    // A cp.async geometry: row = tid>>1 (128 rows), 2 x 16B per thread
    const int arow = tid >> 1;
    const int ac = tid & 1;                    // cols {ac, ac+2} of 4x16B
    const __half* asrc = g_xh + (size_t)toks[arow] * D_DIM;
    const uint32_t sbase = (uint32_t)__cvta_generic_to_shared(smh);
    const uint32_t a_dst = sbase + (uint32_t)(arow * LDA_H * 2);

    // B load geometry
    const int bc4 = tid & 15;
    const int brow = tid >> 4;

    const int wid = tid >> 5;
    const int warpM = wid >> 1, warpN = wid & 1;

    FragC c1[2][2], c3[2][2];
    #pragma unroll
    for (int mi = 0; mi < 2; mi++)
        #pragma unroll
        for (int ni = 0; ni < 2; ni++) {
            wmma::fill_fragment(c1[mi][ni], 0.f);
            wmma::fill_fragment(c3[mi][ni], 0.f);
        }

    const int nchunk = D_DIM / 32;
    float4 rb1[2], rb3[2];

    #define CPA_UP(kc) do { \
        const uint32_t d_ = a_dst + (uint32_t)(((kc) % NST) * STG_UP_H * 2); \
        const __half* s_ = asrc + (kc)*32; \
        cp16(d_ + ac*16,        s_ + ac*8); \
        cp16(d_ + (ac+2)*16,    s_ + (ac+2)*8); \
        cp_commit(); \
    } while (0)

    #define LOAD_B_UP(kc) do { \
        _Pragma("unroll") \
        for (int i_ = 0; i_ < 2; i_++) { \
            rb1[i_] = *(const float4*)(B1 + (size_t)((kc)*32 + brow + i_*16) * ldB + f0 + bc4*4); \
            rb3[i_] = *(const float4*)(B2 + (size_t)((kc)*32 + brow + i_*16) * ldB + f0 + bc4*4); \
        } \
    } while (0)

    #define STS_B_UP(kc) do { \
        __half* St_ = smh + ((kc) % NST) * STG_UP_H; \
        _Pragma("unroll") \
        for (int i_ = 0; i_ < 2; i_++) { \
            sts_f4_h4(St_ + 5120 + (brow + i_*16) * LDB_H + bc4*4, rb1[i_]); \
            sts_f4_h4(St_ + 7424 + (brow + i_*16) * LDB_H + bc4*4, rb3[i_]); \
        } \
    } while (0)

    CPA_UP(0);
    LOAD_B_UP(0);
    STS_B_UP(0);
    CPA_UP(1);
    LOAD_B_UP(1);
    cp_wait<1>();
    __syncthreads();

    for (int kc = 0; kc < nchunk; kc++) {
        const __half* St  = smh + (kc % NST) * STG_UP_H;
        const __half* As  = St;
        const __half* B1s = St + 5120;
        const __half* B2s = St + 7424;
        #pragma unroll
        for (int ks = 0; ks < 2; ks++) {
            FragA a[2];
            #pragma unroll
            for (int mi = 0; mi < 2; mi++)
                wmma::load_matrix_sync(a[mi], As + (warpM*32 + mi*16) * LDA_H + ks*16, LDA_H);
            FragB b;
            #pragma unroll
            for (int ni = 0; ni < 2; ni++) {
                wmma::load_matrix_sync(b, B1s + (ks*16) * LDB_H + warpN*32 + ni*16, LDB_H);
                #pragma unroll
                for (int mi = 0; mi < 2; mi++)
                    wmma::mma_sync(c1[mi][ni], a[mi], b, c1[mi][ni]);
                wmma::load_matrix_sync(b, B2s + (ks*16) * LDB_H + warpN*32 + ni*16, LDB_H);
                #pragma unroll
                for (int mi = 0; mi < 2; mi++)
                    wmma::mma_sync(c3[mi][ni], a[mi], b, c3[mi][ni]);
            }
        }
        if (kc + 1 < nchunk) STS_B_UP(kc + 1);   // regs loaded last iteration
        if (kc + 2 < nchunk) {
            CPA_UP(kc + 2);                       // stage (kc+2)%3: not in use
            LOAD_B_UP(kc + 2);
            cp_wait<1>();                         // A(kc+1) ready
        } else {
            cp_wait<0>();
        }
        __syncthreads();
    }
    #undef CPA_UP
    #undef LOAD_B_UP
    #undef STS_B_UP

    // epilogue: silu(c1)*c3 -> f32 smem C -> masked fp16 copy
    float* Cs = (float*)smh;
    #pragma unroll
    for (int mi = 0; mi < 2; mi++)
        #pragma unroll
        for (int ni = 0; ni < 2; ni++) {
            #pragma unroll
            for (int k = 0; k < c1[mi][ni].num_elements; k++) {
                float v1 = c1[mi][ni].x[k], v3 = c3[mi][ni].x[k];
                c1[mi][ni].x[k] = v1 / (1.f + expf(-v1)) * v3;
            }
            wmma::store_matrix_sync(Cs + (warpM*32 + mi*16) * LDC + warpN*32 + ni*16,
                                    c1[mi][ni], LDC, wmma::mem_row_major);
        }
    __syncthreads();

    int valid = cnt - row0; if (valid > 128) valid = 128;
    #pragma unroll
    for (int i = 0; i < 8; i++) {
        int lin = tid + i * 256;
        int row = lin >> 4, cc = lin & 15;
        if (row < valid) {
            float4 v = *(float4*)(Cs + row * LDC + cc * 4);
            __half2 p0 = __floats2half2_rn(v.x, v.y);
            __half2 p1 = __floats2half2_rn(v.z, v.w);
            uint2 u = make_uint2(*(uint32_t*)&p0, *(uint32_t*)&p1);
            *(uint2*)(dstbuf + (size_t)(base + row0 + row) * ldD + f0 + cc * 4) = u;
        }
    }
}

// ===========================================================================
// Fused down-proj (fp16 MMA): routed (A=g_hbuf, dst=g_dbuf)
//                             shared (A=g_sh, dst=out).
// A via cp.async fp16, B via reg-stage+cvt. 3-stage ring. grid (16, 65, 8).
// ===========================================================================
__global__ void __launch_bounds__(256, 2)
down_fused(const float* __restrict__ w2r,
           const float* __restrict__ w2s,
           float* __restrict__ out) {
    extern __shared__ __half smh[];
    const int tid = threadIdx.x;
    const int y = blockIdx.y;
    const bool se = (y == E_NUM);
    const int d0 = blockIdx.x * 64;
    const int row0 = blockIdx.z * 128;

    int cnt, base, nchunk;
    const float* B1;
    const __half* Abase;
    int ldA;
    float* dstbuf;
    if (se) {
        cnt = NTOK; base = 0;
        B1 = w2s; nchunk = FS_DIM / 32;
        Abase = g_sh; ldA = FS_DIM;
        dstbuf = out;
    } else {
        cnt = g_count[y];
        if (row0 >= cnt) return;
        base = g_offset[y];
        B1 = w2r + (size_t)y * F_DIM * D_DIM;
        nchunk = F_DIM / 32;
        Abase = g_hbuf; ldA = F_DIM;
        dstbuf = g_dbuf;
    }

    // A cp.async geometry
    const int arow = tid >> 1;
    const int ac = tid & 1;
    int rclamp;
    {
        int r = row0 + arow;
        rclamp = (r < cnt) ? r : (cnt - 1);
    }
    const __half* asrc = Abase + (size_t)(base + rclamp) * ldA;
    const uint32_t sbase = (uint32_t)__cvta_generic_to_shared(smh);
    const uint32_t a_dst = sbase + (uint32_t)(arow * LDA_H * 2);

    const int bc4 = tid & 15;
    const int brow = tid >> 4;

    const int wid = tid >> 5;
    const int warpM = wid >> 1, warpN = wid & 1;

    FragC c[2][2];
    #pragma unroll
    for (int mi = 0; mi < 2; mi++)
        #pragma unroll
        for (int ni = 0; ni < 2; ni++)
            wmma::fill_fragment(c[mi][ni], 0.f);

    float4 rB[2];

    #define CPA_DN(kc) do { \
        const uint32_t d_ = a_dst + (uint32_t)(((kc) % NST) * STG_DN_H * 2); \
        const __half* s_ = asrc + (kc)*32; \
        cp16(d_ + ac*16,     s_ + ac*8); \
        cp16(d_ + (ac+2)*16, s_ + (ac+2)*8); \
        cp_commit(); \
    } while (0)

    #define LOAD_B_DN(kc) do { \
        _Pragma("unroll") \
        for (int i_ = 0; i_ < 2; i_++) \
            rB[i_] = *(const float4*)(B1 + (size_t)((kc)*32 + brow + i_*16) * D_DIM + d0 + bc4*4); \
    } while (0)

    #define STS_B_DN(kc) do { \
        __half* St_ = smh + ((kc) % NST) * STG_DN_H; \
        _Pragma("unroll") \
        for (int i_ = 0; i_ < 2; i_++) \
            sts_f4_h4(St_ + 5120 + (brow + i_*16) * LDB_H + bc4*4, rB[i_]); \
    } while (0)

    CPA_DN(0);
    LOAD_B_DN(0);
    STS_B_DN(0);
    CPA_DN(1);
    LOAD_B_DN(1);
    cp_wait<1>();
    __syncthreads();

    for (int kc = 0; kc < nchunk; kc++) {
        const __half* St  = smh + (kc % NST) * STG_DN_H;
        const __half* As  = St;
        const __half* B1s = St + 5120;
        #pragma unroll
        for (int ks = 0; ks < 2; ks++) {
            FragA a[2];
            #pragma unroll
            for (int mi = 0; mi < 2; mi++)
                wmma::load_matrix_sync(a[mi], As + (warpM*32 + mi*16) * LDA_H + ks*16, LDA_H);
            #pragma unroll
            for (int ni = 0; ni < 2; ni++) {
                FragB b;
                wmma::load_matrix_sync(b, B1s + (ks*16) * LDB_H + warpN*32 + ni*16, LDB_H);
                #pragma unroll
                for (int mi = 0; mi < 2; mi++)
                    wmma::mma_sync(c[mi][ni], a[mi], b, c[mi][ni]);
            }
        }
        if (kc + 1 < nchunk) STS_B_DN(kc + 1);
        if (kc + 2 < nchunk) {
            CPA_DN(kc + 2);
            LOAD_B_DN(kc + 2);
            cp_wait<1>();
        } else {
            cp_wait<0>();
        }
        __syncthreads();
    }
    #undef CPA_DN
    #undef LOAD_B_DN
    #undef STS_B_DN

    float* Cs = (float*)smh;
    #pragma unroll
    for (int mi = 0; mi < 2; mi++)
        #pragma unroll
        for (int ni = 0; ni < 2; ni++)
            wmma::store_matrix_sync(Cs + (warpM*32 + mi*16) * LDC + warpN*32 + ni*16,
                                    c[mi][ni], LDC, wmma::mem_row_major);
    __syncthreads();

    int valid = cnt - row0; if (valid > 128) valid = 128;
    #pragma unroll
    for (int i = 0; i < 8; i++) {
        int lin = tid + i * 256;
        int row = lin >> 4, cc = lin & 15;
        if (row < valid) {
            float4 v = *(float4*)(Cs + row * LDC + cc * 4);
            *(float4*)(dstbuf + (size_t)(base + row0 + row) * D_DIM + d0 + cc * 4) = v;
        }
    }
}

// ---------------- combine (applies gate weights) ----------------
__global__ void combine_kernel(float* __restrict__ out) {
    int t = blockIdx.x;
    __shared__ int p[TOPK];
    __shared__ float w[TOPK];
    if (threadIdx.x < TOPK) {
        p[threadIdx.x] = g_tok_pair[t*TOPK + threadIdx.x];
        w[threadIdx.x] = g_tok_w[t*TOPK + threadIdx.x];
    }
    __syncthreads();
    int d = threadIdx.x * 4;
    float4 s = *(float4*)(out + (size_t)t * D_DIM + d);
    #pragma unroll
    for (int k = 0; k < TOPK; k++) {
        const float4 v = *(const float4*)(g_dbuf + (size_t)p[k] * D_DIM + d);
        float wk = w[k];
        s.x += wk*v.x; s.y += wk*v.y; s.z += wk*v.z; s.w += wk*v.w;
    }
    *(float4*)(out + (size_t)t * D_DIM + d) = s;
}

// ---------------------------------------------------------------------------
extern "C" void kernel_launch(void* const* d_in, const int* in_sizes, int n_in,
                              void* d_out, int out_size) {
    const float* x   = (const float*)d_in[0];
    const float* wg  = (const float*)d_in[1];
    const float* gb  = (const float*)d_in[2];
    const float* w1s = (const float*)d_in[3];
    const float* w2s = (const float*)d_in[4];
    const float* w3s = (const float*)d_in[5];
    const float* w1r = (const float*)d_in[6];
    const float* w2r = (const float*)d_in[7];
    const float* w3r = (const float*)d_in[8];
    float* out = (float*)d_out;

    float* scores;
    if (out_size >= NTOK*D_DIM + NTOK*E_NUM) {
        scores = out + (size_t)NTOK * D_DIM;
    } else {
        cudaGetSymbolAddress((void**)&scores, g_scores_scratch);
    }

    static int attr_done = 0;
    if (!attr_done) {
        cudaFuncSetAttribute(up_fused,   cudaFuncAttributeMaxDynamicSharedMemorySize, SMEM_UP_B);
        cudaFuncSetAttribute(down_fused, cudaFuncAttributeMaxDynamicSharedMemorySize, SMEM_DN_B);
        attr_done = 1;
    }

    init_kernel<<<1, 64>>>();
    gate_kernel<<<NTOK, 128>>>(x, wg, gb, scores);
    scan_assign_kernel<<<1, NTOK>>>();

    up_fused<<<dim3(FS_DIM/64, E_NUM + 1, 8), 256, SMEM_UP_B>>>(w1r, w3r, w1s, w3s);
    down_fused<<<dim3(D_DIM/64, E_NUM + 1, 8), 256, SMEM_DN_B>>>(w2r, w2s, out);

    combine_kernel<<<NTOK, 256>>>(out);
}

// round 17
// speedup vs baseline: 1.6070x; 1.6070x over previous
#include <cuda_runtime.h>
#include <cuda_fp16.h>
#include <math.h>
#include <stdint.h>
#include <mma.h>

using namespace nvcuda;

// ---------------- problem constants ----------------
#define D_DIM   1024
#define F_DIM   704
#define E_NUM   64
#define NTOK    1024
#define TOPK    6
#define FS_DIM  1408
#define NPAIR   (NTOK*TOPK)

// ---------------- scratch (static device arrays) ----------------
__device__ __half g_xh[NTOK * D_DIM];        // fp16 copy of x (RN)
__device__ __half g_hbuf[NPAIR * F_DIM];     // fp16 up-proj activations
__device__ float  g_dbuf[NPAIR * D_DIM];
__device__ __half g_sh[NTOK * FS_DIM];       // fp16 shared-expert hidden
__device__ int    g_count[E_NUM];
__device__ int    g_offset[E_NUM];
__device__ int    g_cursor[E_NUM];
__device__ int    g_tok_expert[NTOK*TOPK];
__device__ float  g_tok_w[NTOK*TOPK];
__device__ int    g_tok_pair[NTOK*TOPK];
__device__ int    g_pair_token[NPAIR];
__device__ float  g_pair_w[NPAIR];
__device__ float  g_scores_scratch[NTOK * E_NUM];

// ---------------- smem geometry ----------------
#define LDA_H 40     // halfs per A row (32 + 8 pad); 80B stride, 16B aligned
#define LDB_H 72     // halfs per B row (64 + 8 pad); 144B stride, 16B aligned
#define LDC   68     // floats per C row
// up stage (halfs): A 128*40=5120 @0, B1 32*72=2304 @5120, B2 @7424 -> 9728
#define STG_UP_H 9728
#define TOK_OFF_B (2*STG_UP_H*2)             // 38912
#define SMEM_UP_B (TOK_OFF_B + 512)          // 39424
// down stage (halfs): A 5120 + B 2304 = 7424
#define STG_DN_H 7424
#define SMEM_DN_B 34816                      // max(2*7424*2=29696, C 34816)

// ---------------- WMMA fp16 ----------------
using FragA = wmma::fragment<wmma::matrix_a, 16, 16, 16, __half, wmma::row_major>;
using FragB = wmma::fragment<wmma::matrix_b, 16, 16, 16, __half, wmma::row_major>;
using FragC = wmma::fragment<wmma::accumulator, 16, 16, 16, float>;

__device__ __forceinline__ void sts_f4_h4(__half* dst, float4 v) {
    __half2 p0 = __floats2half2_rn(v.x, v.y);
    __half2 p1 = __floats2half2_rn(v.z, v.w);
    uint2 u = make_uint2(*(uint32_t*)&p0, *(uint32_t*)&p1);
    *(uint2*)dst = u;
}

// ---------------- small kernels ----------------
__global__ void init_kernel() {
    int i = threadIdx.x;
    if (i < E_NUM) { g_count[i] = 0; g_cursor[i] = 0; }
}

// gate + top-k; also emits fp16 copy of x
__global__ void gate_kernel(const float* __restrict__ x,
                            const float* __restrict__ wg,
                            const float* __restrict__ gb,
                            float* __restrict__ scores_out) {
    __shared__ float xs[D_DIM];
    __shared__ float sc[E_NUM];
    int t = blockIdx.x;
    int tid = threadIdx.x;

    const float4* xv = (const float4*)(x + (size_t)t * D_DIM);
    float4* xsv = (float4*)xs;
    for (int i = tid; i < D_DIM/4; i += 128) xsv[i] = xv[i];
    __syncthreads();

    __half2* xh2 = (__half2*)(g_xh + (size_t)t * D_DIM);
    for (int i = tid; i < D_DIM/2; i += 128)
        xh2[i] = __floats2half2_rn(xs[2*i], xs[2*i+1]);

    if (tid < E_NUM) {
        const float4* wv = (const float4*)(wg + (size_t)tid * D_DIM);
        float acc = 0.f;
        #pragma unroll 8
        for (int i = 0; i < D_DIM/4; i++) {
            float4 a = xsv[i]; float4 b = wv[i];
            acc += a.x*b.x + a.y*b.y + a.z*b.z + a.w*b.w;
        }
        float s = 1.f/(1.f + expf(-acc)) + gb[tid];
        sc[tid] = s;
        scores_out[(size_t)t * E_NUM + tid] = s;
    }
    __syncthreads();

    if (tid == 0) {
        float tmp[E_NUM];
        for (int i = 0; i < E_NUM; i++) tmp[i] = sc[i];
        int   sel[TOPK]; float selw[TOPK];
        float wsum = 0.f;
        for (int k = 0; k < TOPK; k++) {
            int bi = 0; float bv = tmp[0];
            for (int i = 1; i < E_NUM; i++)
                if (tmp[i] > bv) { bv = tmp[i]; bi = i; }
            sel[k] = bi; selw[k] = bv; wsum += bv;
            tmp[bi] = -1e30f;
        }
        float inv = 1.f / wsum;
        for (int k = 0; k < TOPK; k++) {
            int e = sel[k];
            g_tok_expert[t*TOPK + k] = e;
            g_tok_w[t*TOPK + k] = selw[k] * inv;
            atomicAdd(&g_count[e], 1);
        }
    }
}

__global__ void scan_assign_kernel() {
    if (threadIdx.x == 0) {
        int acc = 0;
        for (int e = 0; e < E_NUM; e++) { g_offset[e] = acc; acc += g_count[e]; }
    }
    __syncthreads();
    int t = threadIdx.x;
    #pragma unroll
    for (int k = 0; k < TOPK; k++) {
        int e = g_tok_expert[t*TOPK + k];
        int slot = atomicAdd(&g_cursor[e], 1);
        int p = g_offset[e] + slot;
        g_pair_token[p] = t;
        g_pair_w[p] = g_tok_w[t*TOPK + k];
        g_tok_pair[t*TOPK + k] = p;
    }
}

// ===========================================================================
// Fused up-proj (fp16 MMA): routed (y<64, z=2 M-tiles) and
// shared expert (y in [64,68), zidx = (y-64)*2+z -> 8 M-tiles).
// A from g_xh (fp16, raw uint4 stage), B fp32 reg-stage+cvt.
// 256 thr, 8 warps 4x2, BM=128 BN=64 BK=32, 2-stage, prefetch-2, 2 CTAs/SM.
// grid (22, 68, 2).
// ===========================================================================
__global__ void __launch_bounds__(256, 2)
up_fused(const float* __restrict__ w1r,
         const float* __restrict__ w3r,
         const float* __restrict__ w1s,
         const float* __restrict__ w3s) {
    extern __shared__ __half smh[];
    const int tid = threadIdx.x;
    const int y = blockIdx.y;
    const bool se = (y >= E_NUM);
    const int f0 = blockIdx.x * 64;
    const int row0 = (se ? ((y - E_NUM) * 2 + blockIdx.z) : blockIdx.z) * 128;

    int cnt, base, ldB, ldD;
    const float *B1, *B2;
    __half* dstbuf;
    if (se) {
        cnt = NTOK; base = 0;
        B1 = w1s; B2 = w3s; ldB = FS_DIM;
        dstbuf = g_sh; ldD = FS_DIM;
    } else {
        if (f0 >= F_DIM) return;
        cnt = g_count[y];
        if (row0 >= cnt) return;
        base = g_offset[y];
        B1 = w1r + (size_t)y * D_DIM * F_DIM;
        B2 = w3r + (size_t)y * D_DIM * F_DIM;
        ldB = F_DIM;
        dstbuf = g_hbuf; ldD = F_DIM;
    }

    int* toks = (int*)((char*)smh + TOK_OFF_B);
    if (tid < 128) {
        int r = row0 + tid;
        if (se) toks[tid] = r;
        else    toks[tid] = (r < cnt) ? g_pair_token[base + r] : 0;
    }
    __syncthreads();

    // A staging: fp16 source (g_xh), uint4 (16B) raw copies.
    const int c16 = tid & 3;            // uint4 column (row = 64B = 4 x 16B)
    const int arow = tid >> 2;          // rows arow, arow+64
    // B staging: fp32 source, float4 + cvt.
    const int bc4 = tid & 15;
    const int brow = tid >> 4;

    const uint4* arh[2];
    #pragma unroll
    for (int i = 0; i < 2; i++)
        arh[i] = (const uint4*)(g_xh + (size_t)toks[arow + i*64] * D_DIM);

    const int wid = tid >> 5;
    const int warpM = wid >> 1, warpN = wid & 1;   // 4 x 2

    FragC c1[2][2], c3[2][2];
    #pragma unroll
    for (int mi = 0; mi < 2; mi++)
        #pragma unroll
        for (int ni = 0; ni < 2; ni++) {
            wmma::fill_fragment(c1[mi][ni], 0.f);
            wmma::fill_fragment(c3[mi][ni], 0.f);
        }

    const int nchunk = D_DIM / 32;
    uint4 rA[2]; float4 rb1[2], rb3[2];

    #define LOAD_UP(kc) do { \
        _Pragma("unroll") \
        for (int i_ = 0; i_ < 2; i_++) rA[i_] = arh[i_][(kc)*4 + c16]; \
        _Pragma("unroll") \
        for (int i_ = 0; i_ < 2; i_++) { \
            rb1[i_] = *(const float4*)(B1 + (size_t)((kc)*32 + brow + i_*16) * ldB + f0 + bc4*4); \
            rb3[i_] = *(const float4*)(B2 + (size_t)((kc)*32 + brow + i_*16) * ldB + f0 + bc4*4); \
        } \
    } while (0)

    #define STS_UP(kc) do { \
        __half* St_ = smh + ((kc) & 1) * STG_UP_H; \
        _Pragma("unroll") \
        for (int i_ = 0; i_ < 2; i_++) \
            *(uint4*)(St_ + (arow + i_*64) * LDA_H + c16*8) = rA[i_]; \
        _Pragma("unroll") \
        for (int i_ = 0; i_ < 2; i_++) { \
            sts_f4_h4(St_ + 5120 + (brow + i_*16) * LDB_H + bc4*4, rb1[i_]); \
            sts_f4_h4(St_ + 7424 + (brow + i_*16) * LDB_H + bc4*4, rb3[i_]); \
        } \
    } while (0)

    LOAD_UP(0);
    STS_UP(0);
    LOAD_UP(1);
    __syncthreads();

    for (int kc = 0; kc < nchunk; kc++) {
        const __half* St  = smh + (kc & 1) * STG_UP_H;
        const __half* As  = St;
        const __half* B1s = St + 5120;
        const __half* B2s = St + 7424;
        #pragma unroll
        for (int ks = 0; ks < 2; ks++) {
            FragA a[2];
            #pragma unroll
            for (int mi = 0; mi < 2; mi++)
                wmma::load_matrix_sync(a[mi], As + (warpM*32 + mi*16) * LDA_H + ks*16, LDA_H);
            FragB b;
            #pragma unroll
            for (int ni = 0; ni < 2; ni++) {
                wmma::load_matrix_sync(b, B1s + (ks*16) * LDB_H + warpN*32 + ni*16, LDB_H);
                #pragma unroll
                for (int mi = 0; mi < 2; mi++)
                    wmma::mma_sync(c1[mi][ni], a[mi], b, c1[mi][ni]);
                wmma::load_matrix_sync(b, B2s + (ks*16) * LDB_H + warpN*32 + ni*16, LDB_H);
                #pragma unroll
                for (int mi = 0; mi < 2; mi++)
                    wmma::mma_sync(c3[mi][ni], a[mi], b, c3[mi][ni]);
            }
        }
        if (kc + 1 < nchunk) {
            STS_UP(kc + 1);                  // regs loaded one iteration ago
            if (kc + 2 < nchunk) LOAD_UP(kc + 2);
        }
        __syncthreads();
    }
    #undef LOAD_UP
    #undef STS_UP

    // epilogue: silu(c1)*c3 -> f32 smem C -> masked fp16 copy
    float* Cs = (float*)smh;
    #pragma unroll
    for (int mi = 0; mi < 2; mi++)
        #pragma unroll
        for (int ni = 0; ni < 2; ni++) {
            #pragma unroll
            for (int k = 0; k < c1[mi][ni].num_elements; k++) {
                float v1 = c1[mi][ni].x[k], v3 = c3[mi][ni].x[k];
                c1[mi][ni].x[k] = v1 / (1.f + expf(-v1)) * v3;
            }
            wmma::store_matrix_sync(Cs + (warpM*32 + mi*16) * LDC + warpN*32 + ni*16,
                                    c1[mi][ni], LDC, wmma::mem_row_major);
        }
    __syncthreads();

    int valid = cnt - row0; if (valid > 128) valid = 128;
    #pragma unroll
    for (int i = 0; i < 8; i++) {
        int lin = tid + i * 256;
        int row = lin >> 4, cc = lin & 15;
        if (row < valid) {
            float4 v = *(float4*)(Cs + row * LDC + cc * 4);
            __half2 p0 = __floats2half2_rn(v.x, v.y);
            __half2 p1 = __floats2half2_rn(v.z, v.w);
            uint2 u = make_uint2(*(uint32_t*)&p0, *(uint32_t*)&p1);
            *(uint2*)(dstbuf + (size_t)(base + row0 + row) * ldD + f0 + cc * 4) = u;
        }
    }
}

// ===========================================================================
// Fused down-proj (fp16 MMA): routed (y<64, z=2, A=g_hbuf, dst=g_dbuf)
//            shared (y in [64,68), zidx=(y-64)*2+z, A=g_sh, dst=out).
// grid (16, 68, 2).
// ===========================================================================
__global__ void __launch_bounds__(256, 2)
down_fused(const float* __restrict__ w2r,
           const float* __restrict__ w2s,
           float* __restrict__ out) {
    extern __shared__ __half smh[];
    const int tid = threadIdx.x;
    const int y = blockIdx.y;
    const bool se = (y >= E_NUM);
    const int d0 = blockIdx.x * 64;
    const int row0 = (se ? ((y - E_NUM) * 2 + blockIdx.z) : blockIdx.z) * 128;

    int cnt, base, nchunk;
    const float* B1;
    const __half* Abase;
    int ldA;
    float* dstbuf;
    if (se) {
        cnt = NTOK; base = 0;
        B1 = w2s; nchunk = FS_DIM / 32;
        Abase = g_sh; ldA = FS_DIM;
        dstbuf = out;
    } else {
        cnt = g_count[y];
        if (row0 >= cnt) return;
        base = g_offset[y];
        B1 = w2r + (size_t)y * F_DIM * D_DIM;
        nchunk = F_DIM / 32;
        Abase = g_hbuf; ldA = F_DIM;
        dstbuf = g_dbuf;
    }

    const int c16 = tid & 3;
    const int arow4 = tid >> 2;          // rows arow4, arow4+64
    const int bc4 = tid & 15;
    const int brow = tid >> 4;

    const uint4* arh[2];
    #pragma unroll
    for (int i = 0; i < 2; i++) {
        int r = row0 + arow4 + i*64;
        int rr = (r < cnt) ? r : (cnt - 1);
        arh[i] = (const uint4*)(Abase + (size_t)(base + rr) * ldA);
    }

    const int wid = tid >> 5;
    const int warpM = wid >> 1, warpN = wid & 1;

    FragC c[2][2];
    #pragma unroll
    for (int mi = 0; mi < 2; mi++)
        #pragma unroll
        for (int ni = 0; ni < 2; ni++)
            wmma::fill_fragment(c[mi][ni], 0.f);

    uint4 rA[2]; float4 rB[2];

    #define LOAD_DN(kc) do { \
        _Pragma("unroll") \
        for (int i_ = 0; i_ < 2; i_++) rA[i_] = arh[i_][(kc)*4 + c16]; \
        _Pragma("unroll") \
        for (int i_ = 0; i_ < 2; i_++) \
            rB[i_] = *(const float4*)(B1 + (size_t)((kc)*32 + brow + i_*16) * D_DIM + d0 + bc4*4); \
    } while (0)

    #define STS_DN(kc) do { \
        __half* St_ = smh + ((kc) & 1) * STG_DN_H; \
        _Pragma("unroll") \
        for (int i_ = 0; i_ < 2; i_++) \
            *(uint4*)(St_ + (arow4 + i_*64) * LDA_H + c16*8) = rA[i_]; \
        _Pragma("unroll") \
        for (int i_ = 0; i_ < 2; i_++) \
            sts_f4_h4(St_ + 5120 + (brow + i_*16) * LDB_H + bc4*4, rB[i_]); \
    } while (0)

    LOAD_DN(0);
    STS_DN(0);
    if (nchunk > 1) LOAD_DN(1);
    __syncthreads();

    for (int kc = 0; kc < nchunk; kc++) {
        const __half* St  = smh + (kc & 1) * STG_DN_H;
        const __half* As  = St;
        const __half* B1s = St + 5120;
        #pragma unroll
        for (int ks = 0; ks < 2; ks++) {
            FragA a[2];
            #pragma unroll
            for (int mi = 0; mi < 2; mi++)
                wmma::load_matrix_sync(a[mi], As + (warpM*32 + mi*16) * LDA_H + ks*16, LDA_H);
            #pragma unroll
            for (int ni = 0; ni < 2; ni++) {
                FragB b;
                wmma::load_matrix_sync(b, B1s + (ks*16) * LDB_H + warpN*32 + ni*16, LDB_H);
                #pragma unroll
                for (int mi = 0; mi < 2; mi++)
                    wmma::mma_sync(c[mi][ni], a[mi], b, c[mi][ni]);
            }
        }
        if (kc + 1 < nchunk) {
            STS_DN(kc + 1);
            if (kc + 2 < nchunk) LOAD_DN(kc + 2);
        }
        __syncthreads();
    }
    #undef LOAD_DN
    #undef STS_DN

    float* Cs = (float*)smh;
    #pragma unroll
    for (int mi = 0; mi < 2; mi++)
        #pragma unroll
        for (int ni = 0; ni < 2; ni++)
            wmma::store_matrix_sync(Cs + (warpM*32 + mi*16) * LDC + warpN*32 + ni*16,
                                    c[mi][ni], LDC, wmma::mem_row_major);
    __syncthreads();

    int valid = cnt - row0; if (valid > 128) valid = 128;
    #pragma unroll
    for (int i = 0; i < 8; i++) {
        int lin = tid + i * 256;
        int row = lin >> 4, cc = lin & 15;
        if (row < valid) {
            float4 v = *(float4*)(Cs + row * LDC + cc * 4);
            *(float4*)(dstbuf + (size_t)(base + row0 + row) * D_DIM + d0 + cc * 4) = v;
        }
    }
}

// ---------------- combine (applies gate weights) ----------------
__global__ void combine_kernel(float* __restrict__ out) {
    int t = blockIdx.x;
    __shared__ int p[TOPK];
    __shared__ float w[TOPK];
    if (threadIdx.x < TOPK) {
        p[threadIdx.x] = g_tok_pair[t*TOPK + threadIdx.x];
        w[threadIdx.x] = g_tok_w[t*TOPK + threadIdx.x];
    }
    __syncthreads();
    int d = threadIdx.x * 4;
    float4 s = *(float4*)(out + (size_t)t * D_DIM + d);
    #pragma unroll
    for (int k = 0; k < TOPK; k++) {
        const float4 v = *(const float4*)(g_dbuf + (size_t)p[k] * D_DIM + d);
        float wk = w[k];
        s.x += wk*v.x; s.y += wk*v.y; s.z += wk*v.z; s.w += wk*v.w;
    }
    *(float4*)(out + (size_t)t * D_DIM + d) = s;
}

// ---------------------------------------------------------------------------
extern "C" void kernel_launch(void* const* d_in, const int* in_sizes, int n_in,
                              void* d_out, int out_size) {
    const float* x   = (const float*)d_in[0];
    const float* wg  = (const float*)d_in[1];
    const float* gb  = (const float*)d_in[2];
    const float* w1s = (const float*)d_in[3];
    const float* w2s = (const float*)d_in[4];
    const float* w3s = (const float*)d_in[5];
    const float* w1r = (const float*)d_in[6];
    const float* w2r = (const float*)d_in[7];
    const float* w3r = (const float*)d_in[8];
    float* out = (float*)d_out;

    float* scores;
    if (out_size >= NTOK*D_DIM + NTOK*E_NUM) {
        scores = out + (size_t)NTOK * D_DIM;
    } else {
        cudaGetSymbolAddress((void**)&scores, g_scores_scratch);
    }

    static int attr_done = 0;
    if (!attr_done) {
        cudaFuncSetAttribute(up_fused,   cudaFuncAttributeMaxDynamicSharedMemorySize, SMEM_UP_B);
        cudaFuncSetAttribute(down_fused, cudaFuncAttributeMaxDynamicSharedMemorySize, SMEM_DN_B);
        attr_done = 1;
    }

    init_kernel<<<1, 64>>>();
    gate_kernel<<<NTOK, 128>>>(x, wg, gb, scores);
    scan_assign_kernel<<<1, NTOK>>>();

    up_fused<<<dim3(FS_DIM/64, E_NUM + 4, 2), 256, SMEM_UP_B>>>(w1r, w3r, w1s, w3s);
    down_fused<<<dim3(D_DIM/64, E_NUM + 4, 2), 256, SMEM_DN_B>>>(w2r, w2s, out);

    combine_kernel<<<NTOK, 256>>>(out);
}